// round 3
// baseline (speedup 1.0000x reference)
#include <cuda_runtime.h>
#include <cuda_bf16.h>
#include <math.h>

// ---------------------------------------------------------------------------
// MolecularGNN fully fused: embed -> LH gnn layers -> mol sum -> MLP -> out.
// Block-diagonal per molecule => one CTA handles 128 atom rows end-to-end.
// R2 changes: 4x8 GEMM thread-tile (fewer broadcast movs), per-row smem norm
// (no shfl chains), float2 aggregation, float4 embedding gather, 2-launch
// structure (fused kernel resets adjacency counters for the next call).
// ---------------------------------------------------------------------------

#define MAX_T   524288
#define MAX_LAY 8
#define CAP     32          // adjacency slots per node (Poisson(4), max ~19)
#define TILE_ROWS 128

__device__ unsigned      g_cnt[MAX_T];                  // zero-init (.bss)
__device__ unsigned char g_slots[(size_t)MAX_T * CAP];  // local src idx per edge
__device__ float         g_Wt[MAX_LAY * 4096];          // transposed weights

typedef unsigned long long u64;
__device__ __forceinline__ u64 pk2(float x, float y) {
    u64 r; asm("mov.b64 %0,{%1,%2};" : "=l"(r) : "f"(x), "f"(y)); return r;
}
__device__ __forceinline__ u64 bc2(float x) { return pk2(x, x); }
__device__ __forceinline__ void fma2(u64& d, u64 a, u64 b) {
    asm("fma.rn.f32x2 %0,%1,%2,%3;" : "=l"(d) : "l"(a), "l"(b), "l"(d));
}
__device__ __forceinline__ void up2(u64 v, float& x, float& y) {
    asm("mov.b64 {%0,%1},%2;" : "=f"(x), "=f"(y) : "l"(v));
}

// ---------------------------------------------------------------------------
// prep: blocks [0,EB) scatter edges into slot lists; blocks [EB,EB+NW)
// transpose the 64x64 weight matrices. g_cnt is zero on entry (module load
// zero-init for call 1; the fused kernel re-zeroes it for later calls).
__global__ void prep_kernel(const int* __restrict__ src,
                            const int* __restrict__ dst, int E, int S, int EB,
                            const float* __restrict__ Wfp,
                            const float* __restrict__ Wout, int LH) {
    int b = blockIdx.x;
    if (b < EB) {
        int e = b * 256 + threadIdx.x;
        if (e < E) {
            int d = dst[e];
            unsigned idx = atomicAdd(&g_cnt[d], 1u);
            if (idx < CAP) {
                int s = src[e];
                g_slots[(size_t)d * CAP + idx] = (unsigned char)(s - (s / S) * S);
            }
        }
    } else {
        int w = b - EB;
        const float* Ws = (w < LH) ? (Wfp + w * 4096) : (Wout + (w - LH) * 4096);
        float* o = g_Wt + w * 4096;
        for (int i = threadIdx.x; i < 4096; i += blockDim.x) {
            int k = i >> 6, j = i & 63;
            o[i] = Ws[j * 64 + k];          // Wt[k][j] = W[j][k]
        }
    }
}

// ---------------------------------------------------------------------------
// Fused kernel. One CTA: G molecules (G*S <= 128 rows). 256 threads.
// ---------------------------------------------------------------------------
__global__ __launch_bounds__(256, 2)
void gnn_fused_kernel(const int* __restrict__ fp,
                      const float* __restrict__ emb,
                      const float* __restrict__ b_fp,
                      const float* __restrict__ b_out,
                      const float* __restrict__ wprop,
                      const float* __restrict__ bprop,
                      const int* __restrict__ esrc,
                      const int* __restrict__ edst,
                      float* __restrict__ out,
                      int S, int G, int M, int E, int LH, int LO) {
    extern __shared__ float sm[];
    float* v_sh   = sm;                         // 8192 f
    float* h_sh   = sm + 8192;                  // 8192 f
    float* w_sh   = sm + 16384;                 // 4096 f
    float* inv_sh = sm + 20480;                 // 128 f
    unsigned* cnt_sh = (unsigned*)(sm + 20608); // 128 u32
    int*      fpx_sh = (int*)(sm + 20736);      // 128 i32
    unsigned char* slot_sh = (unsigned char*)(sm + 20864); // 4096 B
    unsigned char* mb_sh   = (unsigned char*)(sm + 21888); // 128 B

    const int t = threadIdx.x;
    const int molBase = blockIdx.x * G;
    const int Ga = min(G, M - molBase);
    if (Ga <= 0) return;
    const int GA = Ga * S;
    const int atomBase = molBase * S;

    // thread mappings
    const int tc8 = t & 7,  trg = t >> 3;   // gemm: 8 colgroups x 32 rowgroups
    const int c0 = tc8 * 8, r0 = trg * 4;   //   each thread 4 rows x 8 cols
    const int cp = t & 31,  rg8 = t >> 5;   // agg: 32 colpairs x 8 rowgroups
    const int warp = t >> 5, lane = t & 31;

    // ---- stage adjacency (layer-invariant), fp indices, mol bases ----
    {
        const u64* gs = (const u64*)(g_slots + (size_t)atomBase * CAP);
        u64* ss = (u64*)slot_sh;
        const int nQ = (GA * CAP) >> 3;
        for (int i = t; i < nQ; i += 256) ss[i] = gs[i];
        for (int r = t; r < GA; r += 256) {
            cnt_sh[r] = g_cnt[atomBase + r];
            g_cnt[atomBase + r] = 0u;           // reset for next call
            fpx_sh[r] = fp[atomBase + r] * 16;  // float4-row base into emb
        }
        for (int r = t; r < TILE_ROWS; r += 256)
            mb_sh[r] = (unsigned char)((r / S) * S);
    }
    __syncthreads();

    // ---- embeddings via float4 (padded rows zeroed) ----
    {
        float4* vq = (float4*)v_sh;
        const float4* eq = (const float4*)emb;
        for (int idx = t; idx < GA * 16; idx += 256)
            vq[idx] = eq[fpx_sh[idx >> 4] + (idx & 15)];
        const float4 z = make_float4(0.f, 0.f, 0.f, 0.f);
        for (int idx = GA * 16 + t; idx < TILE_ROWS * 16; idx += 256) vq[idx] = z;
    }

    // ---- GNN layers ----
    for (int l = 0; l < LH; l++) {
        __syncthreads();
        {
            const float4* ws = (const float4*)(g_Wt + l * 4096);
            float4* wd = (float4*)w_sh;
            for (int i = t; i < 1024; i += 256) wd[i] = ws[i];
        }
        float4 bva = *(const float4*)(b_fp + l * 64 + c0);
        float4 bvb = *(const float4*)(b_fp + l * 64 + c0 + 4);
        __syncthreads();

        // GEMM: h = relu(v @ Wt + b). acc[row][colpair], packed f32x2.
        u64 acc[4][4];
#pragma unroll
        for (int i = 0; i < 4; i++) {
            acc[i][0] = pk2(bva.x, bva.y); acc[i][1] = pk2(bva.z, bva.w);
            acc[i][2] = pk2(bvb.x, bvb.y); acc[i][3] = pk2(bvb.z, bvb.w);
        }
#pragma unroll 4
        for (int k = 0; k < 64; k += 4) {
            float vf[4][4];
#pragma unroll
            for (int i = 0; i < 4; i++)
                *(float4*)vf[i] = *(const float4*)&v_sh[(r0 + i) * 64 + k];
#pragma unroll
            for (int kk = 0; kk < 4; kk++) {
                ulonglong2 wa = *(const ulonglong2*)&w_sh[(k + kk) * 64 + c0];
                ulonglong2 wb = *(const ulonglong2*)&w_sh[(k + kk) * 64 + c0 + 4];
#pragma unroll
                for (int i = 0; i < 4; i++) {
                    u64 vb = bc2(vf[i][kk]);
                    fma2(acc[i][0], vb, wa.x); fma2(acc[i][1], vb, wa.y);
                    fma2(acc[i][2], vb, wb.x); fma2(acc[i][3], vb, wb.y);
                }
            }
        }
#pragma unroll
        for (int i = 0; i < 4; i++) {
            float hv[8];
            up2(acc[i][0], hv[0], hv[1]); up2(acc[i][1], hv[2], hv[3]);
            up2(acc[i][2], hv[4], hv[5]); up2(acc[i][3], hv[6], hv[7]);
#pragma unroll
            for (int q = 0; q < 8; q++) hv[q] = fmaxf(hv[q], 0.f);
            *(float4*)&h_sh[(r0 + i) * 64 + c0]     = *(float4*)hv;
            *(float4*)&h_sh[(r0 + i) * 64 + c0 + 4] = *(float4*)(hv + 4);
        }
        __syncthreads();

        // aggregation: v[d] = h[d] + sum_{s in nbr(d)} h[s]  (float2 lanes)
        for (int r = rg8; r < GA; r += 8) {
            unsigned c = cnt_sh[r];
            int mb = mb_sh[r];
            float2 a = *(const float2*)&h_sh[r * 64 + cp * 2];
            if (c <= CAP) {
                const unsigned char* sl = slot_sh + r * CAP;
                for (unsigned e = 0; e < c; e++) {
                    float2 hh = *(const float2*)&h_sh[(mb + sl[e]) * 64 + cp * 2];
                    a.x += hh.x; a.y += hh.y;
                }
            } else {            // never taken for Poisson(4); correctness net
                int n = atomBase + r;
                for (int e = 0; e < E; e++)
                    if (edst[e] == n) {
                        int s = esrc[e];
                        float2 hh = *(const float2*)
                            &h_sh[(mb + (s - (s / S) * S)) * 64 + cp * 2];
                        a.x += hh.x; a.y += hh.y;
                    }
            }
            *(float2*)&v_sh[r * 64 + cp * 2] = a;
        }
        __syncthreads();

        // row L2 norms: one thread per row, rotated float4 dot (no shfl)
        if (warp < 4) {
            int r = warp * 32 + lane;
            float s = 0.f;
            int rot = (r + (r >> 4)) & 15;
#pragma unroll
            for (int i = 0; i < 16; i++) {
                int j = (rot + i) & 15;
                float4 x = *(const float4*)&v_sh[r * 64 + j * 4];
                s += x.x * x.x + x.y * x.y + x.z * x.z + x.w * x.w;
            }
            inv_sh[r] = rsqrtf(fmaxf(s, 1e-24f));
        }
        __syncthreads();
        for (int r = rg8; r < GA; r += 8) {
            float iv = inv_sh[r];
            float2 x = *(const float2*)&v_sh[r * 64 + cp * 2];
            x.x *= iv; x.y *= iv;
            *(float2*)&v_sh[r * 64 + cp * 2] = x;
        }
    }
    __syncthreads();

    // ---- molecule sums ----
    for (int m = rg8; m < Ga; m += 8) {
        float2 s = make_float2(0.f, 0.f);
        for (int i = 0; i < S; i++) {
            float2 x = *(const float2*)&v_sh[(m * S + i) * 64 + cp * 2];
            s.x += x.x; s.y += x.y;
        }
        *(float2*)&h_sh[m * 64 + cp * 2] = s;
    }

    // ---- output MLP ----
    float* cur = h_sh;
    float* nxt = v_sh;
    for (int l = 0; l < LO; l++) {
        __syncthreads();
        {
            const float4* ws = (const float4*)(g_Wt + (LH + l) * 4096);
            float4* wd = (float4*)w_sh;
            for (int i = t; i < 1024; i += 256) wd[i] = ws[i];
        }
        __syncthreads();
        for (int m = rg8; m < Ga; m += 8) {
            float2 a = *(const float2*)&b_out[l * 64 + cp * 2];
#pragma unroll 8
            for (int k = 0; k < 64; k++) {
                float c = cur[m * 64 + k];
                float2 w2 = *(const float2*)&w_sh[k * 64 + cp * 2];
                a.x = fmaf(c, w2.x, a.x); a.y = fmaf(c, w2.y, a.y);
            }
            a.x = fmaxf(a.x, 0.f); a.y = fmaxf(a.y, 0.f);
            *(float2*)&nxt[m * 64 + cp * 2] = a;
        }
        float* tmp = cur; cur = nxt; nxt = tmp;
    }
    __syncthreads();

    // ---- final dot ----
    for (int m = warp; m < Ga; m += 8) {
        float s = cur[m * 64 + lane] * wprop[lane]
                + cur[m * 64 + 32 + lane] * wprop[32 + lane];
#pragma unroll
        for (int o = 16; o; o >>= 1) s += __shfl_xor_sync(0xffffffffu, s, o);
        if (lane == 0) out[molBase + m] = s + bprop[0];
    }
}

// ---------------------------------------------------------------------------

extern "C" void kernel_launch(void* const* d_in, const int* in_sizes, int n_in,
                              void* d_out, int out_size) {
    const float* emb    = (const float*)d_in[0];
    const float* W_fp   = (const float*)d_in[1];
    const float* b_fp   = (const float*)d_in[2];
    const float* W_out  = (const float*)d_in[3];
    const float* b_out  = (const float*)d_in[4];
    const float* W_prop = (const float*)d_in[5];
    const float* b_prop = (const float*)d_in[6];
    const int*   fp     = (const int*)d_in[7];
    const int*   esrc   = (const int*)d_in[8];
    const int*   edst   = (const int*)d_in[9];

    float* out = (float*)d_out;

    const int M  = out_size;
    const int T  = in_sizes[7];
    const int E  = in_sizes[8];
    const int LH = in_sizes[2] / 64;
    const int LO = in_sizes[4] / 64;
    const int S  = T / M;
    int G = TILE_ROWS / S;
    if (G < 1) G = 1;

    const int EB = (E + 255) / 256;
    const int NW = LH + LO;
    prep_kernel<<<EB + NW, 256>>>(esrc, edst, E, S, EB, W_fp, W_out, LH);

    const int smemBytes = 21888 * 4 + 128;      // 87680 B
    cudaFuncSetAttribute(gnn_fused_kernel,
                         cudaFuncAttributeMaxDynamicSharedMemorySize, smemBytes);
    const int nBlocks = (M + G - 1) / G;
    gnn_fused_kernel<<<nBlocks, 256, smemBytes>>>(fp, emb, b_fp, b_out,
                                                  W_prop, b_prop, esrc, edst, out,
                                                  S, G, M, E, LH, LO);
}

// round 4
// speedup vs baseline: 1.3922x; 1.3922x over previous
#include <cuda_runtime.h>
#include <cuda_bf16.h>
#include <math.h>

// ---------------------------------------------------------------------------
// MolecularGNN fully fused. R3 changes (target: l1tex 75% -> ~55%):
//  - XOR bank swizzle on v/h tiles (quad' = quad ^ ((row>>2)&7))
//  - w-read column remap {tc8*4, tc8*4+32}: 1-phase LDS per w instruction
//  - normalization scale folded into next GEMM's v-read (no scale pass)
//  - norm (warps 0-3) overlapped with next-layer weight staging (warps 4-7)
// ---------------------------------------------------------------------------

#define MAX_T   524288
#define MAX_LAY 8
#define CAP     32
#define TILE_ROWS 128

__device__ unsigned      g_cnt[MAX_T];                  // zero-init (.bss)
__device__ unsigned char g_slots[(size_t)MAX_T * CAP];
__device__ float         g_Wt[MAX_LAY * 4096];

typedef unsigned long long u64;
__device__ __forceinline__ u64 pk2(float x, float y) {
    u64 r; asm("mov.b64 %0,{%1,%2};" : "=l"(r) : "f"(x), "f"(y)); return r;
}
__device__ __forceinline__ u64 bc2(float x) { return pk2(x, x); }
__device__ __forceinline__ void fma2(u64& d, u64 a, u64 b) {
    asm("fma.rn.f32x2 %0,%1,%2,%3;" : "=l"(d) : "l"(a), "l"(b), "l"(d));
}
__device__ __forceinline__ void up2(u64 v, float& x, float& y) {
    asm("mov.b64 {%0,%1},%2;" : "=f"(x), "=f"(y) : "l"(v));
}
// swizzled float-offset of (row, quad q, word-in-quad wo)
__device__ __forceinline__ int vadr(int row, int q, int wo) {
    return row * 64 + (((q ^ ((row >> 2) & 7)) << 2) + wo);
}

// ---------------------------------------------------------------------------
__global__ void prep_kernel(const int* __restrict__ src,
                            const int* __restrict__ dst, int E, int S, int EB,
                            const float* __restrict__ Wfp,
                            const float* __restrict__ Wout, int LH) {
    int b = blockIdx.x;
    if (b < EB) {
        int e = b * 256 + threadIdx.x;
        if (e < E) {
            int d = dst[e];
            unsigned idx = atomicAdd(&g_cnt[d], 1u);
            if (idx < CAP) {
                int s = src[e];
                g_slots[(size_t)d * CAP + idx] = (unsigned char)(s - (s / S) * S);
            }
        }
    } else {
        int w = b - EB;
        const float* Ws = (w < LH) ? (Wfp + w * 4096) : (Wout + (w - LH) * 4096);
        float* o = g_Wt + w * 4096;
        for (int i = threadIdx.x; i < 4096; i += blockDim.x) {
            int k = i >> 6, j = i & 63;
            o[i] = Ws[j * 64 + k];
        }
    }
}

// ---------------------------------------------------------------------------
__global__ __launch_bounds__(256, 2)
void gnn_fused_kernel(const int* __restrict__ fp,
                      const float* __restrict__ emb,
                      const float* __restrict__ b_fp,
                      const float* __restrict__ b_out,
                      const float* __restrict__ wprop,
                      const float* __restrict__ bprop,
                      const int* __restrict__ esrc,
                      const int* __restrict__ edst,
                      float* __restrict__ out,
                      int S, int G, int M, int E, int LH, int LO) {
    extern __shared__ float sm[];
    float* v_sh   = sm;                         // 8192 f (swizzled)
    float* h_sh   = sm + 8192;                  // 8192 f (swizzled)
    float* w_sh   = sm + 16384;                 // 4096 f (plain [k][c])
    float* inv_sh = sm + 20480;                 // 128 f
    unsigned* cnt_sh = (unsigned*)(sm + 20608); // 128 u32
    int*      fpx_sh = (int*)(sm + 20736);      // 128 i32
    unsigned char* slot_sh = (unsigned char*)(sm + 20864); // 4096 B
    unsigned char* mb_sh   = (unsigned char*)(sm + 21888); // 128 B

    const int t = threadIdx.x;
    const int molBase = blockIdx.x * G;
    const int Ga = min(G, M - molBase);
    if (Ga <= 0) return;
    const int GA = Ga * S;
    const int atomBase = molBase * S;

    const int tc8 = t & 7, trg = t >> 3;    // gemm: 8 colgroups x 32 rowgroups
    const int c0a = tc8 * 4, c0b = c0a + 32, r0 = trg * 4;
    const int cp = t & 31, rg8 = t >> 5;    // agg: 32 colpairs x 8 rowgroups
    const int aq = cp >> 1, awo = (cp & 1) * 2;
    const int warp = t >> 5, lane = t & 31;

    // ---- stage adjacency, fp indices, mol bases, layer-0 weights ----
    {
        const u64* gs = (const u64*)(g_slots + (size_t)atomBase * CAP);
        u64* ss = (u64*)slot_sh;
        const int nQ = (GA * CAP) >> 3;
        for (int i = t; i < nQ; i += 256) ss[i] = gs[i];
        for (int r = t; r < GA; r += 256) {
            cnt_sh[r] = g_cnt[atomBase + r];
            g_cnt[atomBase + r] = 0u;
            fpx_sh[r] = fp[atomBase + r] * 16;
        }
        for (int r = t; r < TILE_ROWS; r += 256)
            mb_sh[r] = (unsigned char)((r / S) * S);
        const float4* ws = (const float4*)g_Wt;
        float4* wd = (float4*)w_sh;
        for (int i = t; i < 1024; i += 256) wd[i] = ws[i];
    }
    __syncthreads();

    // ---- embeddings (swizzled store, padded rows zeroed) ----
    {
        const float4* eq = (const float4*)emb;
        for (int idx = t; idx < GA * 16; idx += 256) {
            int r = idx >> 4, q = idx & 15;
            *(float4*)&v_sh[vadr(r, q, 0)] = eq[fpx_sh[r] + q];
        }
        const float4 z = make_float4(0.f, 0.f, 0.f, 0.f);
        for (int idx = GA * 16 + t; idx < TILE_ROWS * 16; idx += 256)
            *(float4*)&v_sh[vadr(idx >> 4, idx & 15, 0)] = z;
    }

    // ---- GNN layers ----
    for (int l = 0; l < LH; l++) {
        __syncthreads();            // v, w_sh(l), inv(l-1) ready

        float ivr[4];
        if (l) {
#pragma unroll
            for (int i = 0; i < 4; i++) ivr[i] = inv_sh[r0 + i];
        } else {
#pragma unroll
            for (int i = 0; i < 4; i++) ivr[i] = 1.f;
        }
        float4 bva = *(const float4*)(b_fp + l * 64 + c0a);
        float4 bvb = *(const float4*)(b_fp + l * 64 + c0b);

        // GEMM: h = relu((v*inv) @ Wt + b)
        u64 acc[4][4];
#pragma unroll
        for (int i = 0; i < 4; i++) {
            acc[i][0] = pk2(bva.x, bva.y); acc[i][1] = pk2(bva.z, bva.w);
            acc[i][2] = pk2(bvb.x, bvb.y); acc[i][3] = pk2(bvb.z, bvb.w);
        }
        const int vcol = ((0 ^ (trg & 7)) << 2);  // swizzle const for this thread
#pragma unroll 4
        for (int k = 0; k < 64; k += 4) {
            const int co = (((k >> 2) ^ (trg & 7)) << 2);
            float vf[4][4];
#pragma unroll
            for (int i = 0; i < 4; i++)
                *(float4*)vf[i] = *(const float4*)&v_sh[(r0 + i) * 64 + co];
#pragma unroll
            for (int kk = 0; kk < 4; kk++) {
                ulonglong2 wa = *(const ulonglong2*)&w_sh[(k + kk) * 64 + c0a];
                ulonglong2 wb = *(const ulonglong2*)&w_sh[(k + kk) * 64 + c0b];
#pragma unroll
                for (int i = 0; i < 4; i++) {
                    u64 vb = bc2(vf[i][kk] * ivr[i]);
                    fma2(acc[i][0], vb, wa.x); fma2(acc[i][1], vb, wa.y);
                    fma2(acc[i][2], vb, wb.x); fma2(acc[i][3], vb, wb.y);
                }
            }
        }
        (void)vcol;
#pragma unroll
        for (int i = 0; i < 4; i++) {
            float hv[8];
            up2(acc[i][0], hv[0], hv[1]); up2(acc[i][1], hv[2], hv[3]);
            up2(acc[i][2], hv[4], hv[5]); up2(acc[i][3], hv[6], hv[7]);
#pragma unroll
            for (int q = 0; q < 8; q++) hv[q] = fmaxf(hv[q], 0.f);
            int row = r0 + i;
            *(float4*)&h_sh[vadr(row, tc8, 0)]     = *(float4*)hv;
            *(float4*)&h_sh[vadr(row, tc8 + 8, 0)] = *(float4*)(hv + 4);
        }
        __syncthreads();

        // aggregation: v[d] = h[d] + sum_nbr h[s]   (swizzled rows)
        for (int r = rg8; r < GA; r += 8) {
            unsigned c = cnt_sh[r];
            int mb = mb_sh[r];
            float2 a = *(const float2*)&h_sh[vadr(r, aq, awo)];
            if (c <= CAP) {
                const unsigned char* sl = slot_sh + r * CAP;
                for (unsigned e = 0; e < c; e++) {
                    int nr = mb + sl[e];
                    float2 hh = *(const float2*)&h_sh[vadr(nr, aq, awo)];
                    a.x += hh.x; a.y += hh.y;
                }
            } else {            // unreachable for Poisson(4); correctness net
                int n = atomBase + r;
                for (int e = 0; e < E; e++)
                    if (edst[e] == n) {
                        int s = esrc[e];
                        int nr = mb + (s - (s / S) * S);
                        float2 hh = *(const float2*)&h_sh[vadr(nr, aq, awo)];
                        a.x += hh.x; a.y += hh.y;
                    }
            }
            *(float2*)&v_sh[vadr(r, aq, awo)] = a;
        }
        __syncthreads();

        // norm (warps 0-3) overlapped with next-layer weight staging (4-7)
        if (warp < 4) {
            int r = warp * 32 + lane;
            float s = 0.f;
#pragma unroll
            for (int i = 0; i < 16; i++) {
                int q = (i + (r & 15)) & 15;
                float4 x = *(const float4*)&v_sh[vadr(r, q, 0)];
                s += x.x * x.x + x.y * x.y + x.z * x.z + x.w * x.w;
            }
            inv_sh[r] = rsqrtf(fmaxf(s, 1e-24f));
        } else {
            const float4* ws = (const float4*)(g_Wt + (l + 1) * 4096);
            float4* wd = (float4*)w_sh;
            for (int i = t - 128; i < 1024; i += 128) wd[i] = ws[i];
        }
    }
    __syncthreads();    // inv(last), v ready; w_sh = MLP layer 0

    // ---- molecule sums (apply final inv here) ----
    for (int m = rg8; m < Ga; m += 8) {
        float2 s = make_float2(0.f, 0.f);
        for (int i = 0; i < S; i++) {
            int r = m * S + i;
            float iv = inv_sh[r];
            float2 x = *(const float2*)&v_sh[vadr(r, aq, awo)];
            s.x = fmaf(x.x, iv, s.x); s.y = fmaf(x.y, iv, s.y);
        }
        *(float2*)&h_sh[m * 64 + cp * 2] = s;   // plain layout for MLP
    }

    // ---- output MLP (plain layout) ----
    float* cur = h_sh;
    float* nxt = v_sh;
    for (int l = 0; l < LO; l++) {
        if (l > 0) {
            __syncthreads();
            const float4* ws = (const float4*)(g_Wt + (LH + l) * 4096);
            float4* wd = (float4*)w_sh;
            for (int i = t; i < 1024; i += 256) wd[i] = ws[i];
        }
        __syncthreads();
        for (int m = rg8; m < Ga; m += 8) {
            float2 a = *(const float2*)&b_out[l * 64 + cp * 2];
#pragma unroll 8
            for (int k = 0; k < 64; k++) {
                float c = cur[m * 64 + k];
                float2 w2 = *(const float2*)&w_sh[k * 64 + cp * 2];
                a.x = fmaf(c, w2.x, a.x); a.y = fmaf(c, w2.y, a.y);
            }
            a.x = fmaxf(a.x, 0.f); a.y = fmaxf(a.y, 0.f);
            *(float2*)&nxt[m * 64 + cp * 2] = a;
        }
        float* tmp = cur; cur = nxt; nxt = tmp;
    }
    __syncthreads();

    // ---- final dot ----
    for (int m = warp; m < Ga; m += 8) {
        float s = cur[m * 64 + lane] * wprop[lane]
                + cur[m * 64 + 32 + lane] * wprop[32 + lane];
#pragma unroll
        for (int o = 16; o; o >>= 1) s += __shfl_xor_sync(0xffffffffu, s, o);
        if (lane == 0) out[molBase + m] = s + bprop[0];
    }
}

// ---------------------------------------------------------------------------

extern "C" void kernel_launch(void* const* d_in, const int* in_sizes, int n_in,
                              void* d_out, int out_size) {
    const float* emb    = (const float*)d_in[0];
    const float* W_fp   = (const float*)d_in[1];
    const float* b_fp   = (const float*)d_in[2];
    const float* W_out  = (const float*)d_in[3];
    const float* b_out  = (const float*)d_in[4];
    const float* W_prop = (const float*)d_in[5];
    const float* b_prop = (const float*)d_in[6];
    const int*   fp     = (const int*)d_in[7];
    const int*   esrc   = (const int*)d_in[8];
    const int*   edst   = (const int*)d_in[9];

    float* out = (float*)d_out;

    const int M  = out_size;
    const int T  = in_sizes[7];
    const int E  = in_sizes[8];
    const int LH = in_sizes[2] / 64;
    const int LO = in_sizes[4] / 64;
    const int S  = T / M;
    int G = TILE_ROWS / S;
    if (G < 1) G = 1;

    const int EB = (E + 255) / 256;
    prep_kernel<<<EB + LH + LO, 256>>>(esrc, edst, E, S, EB, W_fp, W_out, LH);

    const int smemBytes = 21888 * 4 + 128;
    cudaFuncSetAttribute(gnn_fused_kernel,
                         cudaFuncAttributeMaxDynamicSharedMemorySize, smemBytes);
    const int nBlocks = (M + G - 1) / G;
    gnn_fused_kernel<<<nBlocks, 256, smemBytes>>>(fp, emb, b_fp, b_out,
                                                  W_prop, b_prop, esrc, edst, out,
                                                  S, G, M, E, LH, LO);
}